// round 6
// baseline (speedup 1.0000x reference)
#include <cuda_runtime.h>
#include <cuda_bf16.h>
#include <math.h>
#include <stdint.h>

// Problem constants
#define BB 32
#define TT 512
#define WW 250
#define DD 768
#define GG 3072       // 4*D
#define MROWS 8000    // B*W
#define H2 1536       // 2*D

// ------------------- device scratch (static globals; no allocs) -------------------
__device__ float g_feat[MROWS * DD];
__device__ float g_pre0[MROWS * GG];
__device__ float g_pre1[MROWS * GG];
__device__ float g_h1[MROWS * H2];
__device__ float g_h2[MROWS * H2];
__device__ float g_emis[MROWS * 2];
__device__ float g_hT[2][2][DD][BB];       // [parity][dir][k][b]  transposed h
__device__ int   g_first[MROWS];
__device__ unsigned char g_bp[BB][WW][2];
__device__ unsigned g_cnt[2] = {0, 0};     // per-dir barrier count
__device__ unsigned g_gen[2] = {0, 0};     // per-dir barrier generation
__device__ int g_w64 = 0;

// ------------------- int64 vs int32 detection -------------------
__global__ void detect_kernel(const int* __restrict__ w) {
    __shared__ int bad;
    if (threadIdx.x == 0) bad = 0;
    __syncthreads();
    for (int i = threadIdx.x; i < 8192; i += blockDim.x) {
        int v = w[2 * i + 1];
        if (v != 0 && v != -1) bad = 1;
    }
    __syncthreads();
    if (threadIdx.x == 0) g_w64 = bad ? 0 : 1;
}

// ------------------- first-subtoken index -------------------
__global__ void firstidx_kernel(const int* __restrict__ w) {
    int id = blockIdx.x * blockDim.x + threadIdx.x;
    if (id >= MROWS) return;
    int b = id / WW, ww = id % WW;
    int mul = g_w64 ? 2 : 1;
    const int* row = w + (size_t)b * TT * mul;
    int idx = TT - 1;
    for (int t = 0; t < TT; t++) {
        if (row[t * mul] == ww) { idx = t; break; }
    }
    g_first[id] = idx;
}

// ------------------- gather feat rows -------------------
__global__ void gather_kernel(const float* __restrict__ bert) {
    int row = blockIdx.x;
    int fi = g_first[row];
    int b = row / WW;
    const float4* src = (const float4*)(bert + ((size_t)b * TT + fi) * DD);
    float4* dst = (float4*)(g_feat + (size_t)row * DD);
    for (int i = threadIdx.x; i < DD / 4; i += blockDim.x) dst[i] = src[i];
}

// ------------------- fp32 GEMM: C[m][n] = sum_k A[m][k]*B[n][k] + bias[n] -------------------
#define BM 128
#define BN 128
#define BKK 8
__global__ __launch_bounds__(256) void gemm_bias_kernel(
    const float* __restrict__ A, const float* __restrict__ B,
    const float* __restrict__ bias, float* __restrict__ C,
    int M, int N, int K)
{
    __shared__ float As[2][BKK][BM];
    __shared__ float Bs[2][BKK][BN];
    int tid = threadIdx.x;
    int m0 = blockIdx.y * BM;
    int n0 = blockIdx.x * BN;

    int lr = tid >> 1;
    int lk = (tid & 1) * 4;
    int ty = tid >> 4;
    int tx = tid & 15;

    float acc[8][8];
#pragma unroll
    for (int r = 0; r < 8; r++)
#pragma unroll
        for (int c = 0; c < 8; c++) acc[r][c] = 0.f;

    int nIter = K / BKK;
    float4 aReg, bReg;

    {
        int m = m0 + lr;
        aReg = (m < M) ? *(const float4*)(A + (size_t)m * K + lk)
                       : make_float4(0.f, 0.f, 0.f, 0.f);
        bReg = *(const float4*)(B + (size_t)(n0 + lr) * K + lk);
        As[0][lk + 0][lr] = aReg.x; As[0][lk + 1][lr] = aReg.y;
        As[0][lk + 2][lr] = aReg.z; As[0][lk + 3][lr] = aReg.w;
        Bs[0][lk + 0][lr] = bReg.x; Bs[0][lk + 1][lr] = bReg.y;
        Bs[0][lk + 2][lr] = bReg.z; Bs[0][lk + 3][lr] = bReg.w;
    }
    __syncthreads();

    int cur = 0;
    for (int it = 0; it < nIter; ++it) {
        if (it + 1 < nIter) {
            int k0 = (it + 1) * BKK;
            int m = m0 + lr;
            aReg = (m < M) ? *(const float4*)(A + (size_t)m * K + k0 + lk)
                           : make_float4(0.f, 0.f, 0.f, 0.f);
            bReg = *(const float4*)(B + (size_t)(n0 + lr) * K + k0 + lk);
        }
#pragma unroll
        for (int k = 0; k < BKK; k++) {
            float a_[8], b_[8];
            *(float4*)&a_[0] = *(const float4*)&As[cur][k][ty * 8];
            *(float4*)&a_[4] = *(const float4*)&As[cur][k][ty * 8 + 4];
            *(float4*)&b_[0] = *(const float4*)&Bs[cur][k][tx * 8];
            *(float4*)&b_[4] = *(const float4*)&Bs[cur][k][tx * 8 + 4];
#pragma unroll
            for (int r = 0; r < 8; r++)
#pragma unroll
                for (int c = 0; c < 8; c++)
                    acc[r][c] = fmaf(a_[r], b_[c], acc[r][c]);
        }
        if (it + 1 < nIter) {
            cur ^= 1;
            As[cur][lk + 0][lr] = aReg.x; As[cur][lk + 1][lr] = aReg.y;
            As[cur][lk + 2][lr] = aReg.z; As[cur][lk + 3][lr] = aReg.w;
            Bs[cur][lk + 0][lr] = bReg.x; Bs[cur][lk + 1][lr] = bReg.y;
            Bs[cur][lk + 2][lr] = bReg.z; Bs[cur][lk + 3][lr] = bReg.w;
            __syncthreads();
        }
    }

#pragma unroll
    for (int r = 0; r < 8; r++) {
        int m = m0 + ty * 8 + r;
        if (m < M) {
#pragma unroll
            for (int c = 0; c < 8; c++) {
                int n = n0 + tx * 8 + c;
                C[(size_t)m * N + n] = acc[r][c] + bias[n];
            }
        }
    }
}

// ------------------- TMA / mbarrier helpers -------------------
__device__ __forceinline__ uint32_t smem_u32(const void* p) {
    uint32_t a;
    asm("{ .reg .u64 t; cvta.to.shared.u64 t, %1; cvt.u32.u64 %0, t; }"
        : "=r"(a) : "l"(p));
    return a;
}
__device__ __forceinline__ void mbar_init(uint32_t addr, uint32_t count) {
    asm volatile("mbarrier.init.shared.b64 [%0], %1;" :: "r"(addr), "r"(count) : "memory");
}
__device__ __forceinline__ void mbar_wait(uint32_t addr, uint32_t phase) {
    uint32_t done;
    do {
        asm volatile(
            "{\n\t.reg .pred p;\n\t"
            "mbarrier.try_wait.parity.acquire.cta.shared::cta.b64 p, [%1], %2, 0x989680;\n\t"
            "selp.b32 %0, 1, 0, p;\n\t}"
            : "=r"(done) : "r"(addr), "r"(phase) : "memory");
    } while (!done);
}
__device__ __forceinline__ void tma_fetch(uint32_t mbar, uint32_t dst_smem,
                                          const void* src_gmem, uint32_t bytes) {
    asm volatile("mbarrier.arrive.expect_tx.shared.b64 _, [%0], %1;"
                 :: "r"(mbar), "r"(bytes) : "memory");
    asm volatile(
        "cp.async.bulk.shared::cluster.global.mbarrier::complete_tx::bytes "
        "[%0], [%1], %2, [%3];"
        :: "r"(dst_smem), "l"(src_gmem), "r"(bytes), "r"(mbar) : "memory");
}

// ------------------- persistent LSTM layer kernel -------------------
// 128 CTAs x 256 threads; CTA 0-63: forward, 64-127: reverse. 12 units/CTA.
// W_hh tile resident in SMEM across all 250 steps. h exchanged via g_hT (L2);
// staged into a 3-slot SMEM ring via cp.async.bulk (2-deep pipeline).
#define NCTA_DIR 64
#define HCHUNK_BYTES (128 * BB * 4)   // 16384 B: 128 k-values x 32 batches

__device__ __forceinline__ void dir_barrier(int dir) {
    __threadfence();
    __syncthreads();
    if (threadIdx.x == 0) {
        unsigned my = *(volatile unsigned*)&g_gen[dir];
        unsigned t = atomicAdd(&g_cnt[dir], 1u);
        if (t == NCTA_DIR - 1) {
            g_cnt[dir] = 0;
            __threadfence();
            atomicAdd(&g_gen[dir], 1u);
        } else {
            while (*(volatile unsigned*)&g_gen[dir] == my) { __nanosleep(64); }
            __threadfence();
        }
    }
    __syncthreads();
}

__global__ __launch_bounds__(256) void lstm_persist_kernel(
    const float* __restrict__ preF, const float* __restrict__ preR,
    const float* __restrict__ whhF, const float* __restrict__ whhR,
    float* __restrict__ hout)
{
    extern __shared__ float sm[];
    float* w_s    = sm;                      // 48*768     = 36864 floats
    float* h_s    = w_s + 48 * DD;           // 3*128*32   = 12288
    float* gate_s = h_s + 3 * 128 * BB;      // 48*32      =  1536
    float* c_s    = gate_s + 48 * BB;        // 12*32      =   384
    __shared__ __align__(8) unsigned long long mbar_arr[3];

    int tid = threadIdx.x, bid = blockIdx.x;
    int dir = bid >> 6;
    int U0 = (bid & 63) * 12;
    const float* whh = dir ? whhR : whhF;
    const float* pre = dir ? preR : preF;

    int warp = tid >> 5, lane = tid & 31;
    int r0 = warp * 6;                       // this warp's 6 gate rows

    uint32_t mbar0 = smem_u32(&mbar_arr[0]);
    uint32_t hsm0  = smem_u32(h_s);

    if (tid == 0) {
        mbar_init(mbar0 + 0, 1);
        mbar_init(mbar0 + 8, 1);
        mbar_init(mbar0 + 16, 1);
    }

    // One-time cooperative W load. Row r (0..47): gate g=r/12, unit u=r%12.
    for (int idx = tid; idx < 48 * (DD / 4); idx += 256) {
        int r = idx / (DD / 4), k4 = idx % (DD / 4);
        int g = r / 12, u = r % 12;
        *(float4*)&w_s[r * DD + k4 * 4] =
            *(const float4*)(whh + ((size_t)(g * DD + U0 + u)) * DD + k4 * 4);
    }
    for (int idx = tid; idx < 12 * BB; idx += 256) c_s[idx] = 0.f;
    __syncthreads();

    uint32_t phbits = 0;   // per-slot mbarrier phase (bits 0..2), same on all threads

    for (int s = 0; s < WW; ++s) {
        int t = dir ? (WW - 1 - s) : s;
        float acc[6] = {0.f, 0.f, 0.f, 0.f, 0.f, 0.f};

        if (s > 0) {
            const char* hsrc = (const char*)&g_hT[(s - 1) & 1][dir][0][0];
            if (tid == 0) {
                asm volatile("fence.proxy.async;" ::: "memory");
                tma_fetch(mbar0 + 0, hsm0 + 0 * HCHUNK_BYTES,
                          hsrc + 0 * HCHUNK_BYTES, HCHUNK_BYTES);
                tma_fetch(mbar0 + 8, hsm0 + 1 * HCHUNK_BYTES,
                          hsrc + 1 * HCHUNK_BYTES, HCHUNK_BYTES);
            }
#pragma unroll 1
            for (int c = 0; c < 6; c++) {
                int slot = c % 3;
                mbar_wait(mbar0 + slot * 8, (phbits >> slot) & 1u);
                phbits ^= (1u << slot);
                __syncthreads();   // all warps done with chunk c-1 -> safe to refill
                if (tid == 0 && c < 4) {
                    int s2 = (c + 2) % 3;
                    tma_fetch(mbar0 + s2 * 8, hsm0 + s2 * HCHUNK_BYTES,
                              hsrc + (size_t)(c + 2) * HCHUNK_BYTES, HCHUNK_BYTES);
                }
                const float* hb = h_s + slot * (128 * BB);
#pragma unroll 4
                for (int kk = 0; kk < 128; kk += 4) {
                    float h0 = hb[(kk + 0) * BB + lane];
                    float h1 = hb[(kk + 1) * BB + lane];
                    float h2v = hb[(kk + 2) * BB + lane];
                    float h3 = hb[(kk + 3) * BB + lane];
#pragma unroll
                    for (int j = 0; j < 6; j++) {
                        float4 wv = *(const float4*)&w_s[(r0 + j) * DD + c * 128 + kk];
                        acc[j] = fmaf(wv.x, h0, acc[j]);
                        acc[j] = fmaf(wv.y, h1, acc[j]);
                        acc[j] = fmaf(wv.z, h2v, acc[j]);
                        acc[j] = fmaf(wv.w, h3, acc[j]);
                    }
                }
            }
        }

        // publish gate partials (lane = batch)
#pragma unroll
        for (int j = 0; j < 6; j++) gate_s[(r0 + j) * BB + lane] = acc[j];
        __syncthreads();

        // elementwise LSTM cell: 12 units x 32 batches = 384 items, strided
        for (int item = tid; item < 12 * BB; item += 256) {
            int u = item >> 5, b = item & 31;
            size_t base = ((size_t)(b * WW + t)) * GG + U0 + u;
            float gi = gate_s[(0 * 12 + u) * BB + b] + pre[base + 0 * DD];
            float gf = gate_s[(1 * 12 + u) * BB + b] + pre[base + 1 * DD];
            float gg = gate_s[(2 * 12 + u) * BB + b] + pre[base + 2 * DD];
            float go = gate_s[(3 * 12 + u) * BB + b] + pre[base + 3 * DD];
            float iv = 1.f / (1.f + expf(-gi));
            float fv = 1.f / (1.f + expf(-gf));
            float gv = tanhf(gg);
            float ov = 1.f / (1.f + expf(-go));
            float cc = fv * c_s[u * BB + b] + iv * gv;
            c_s[u * BB + b] = cc;
            float hh = ov * tanhf(cc);
            __stcg(&g_hT[s & 1][dir][U0 + u][b], hh);
            hout[((size_t)(b * WW + t)) * H2 + dir * DD + U0 + u] = hh;
        }

        if (s < WW - 1) dir_barrier(dir);
    }
}

// ------------------- emissions: linear (NT=2) + softmax -------------------
__global__ void emis_kernel(const float* __restrict__ h2,
                            const float* __restrict__ wlin,
                            const float* __restrict__ blin,
                            float* __restrict__ out)
{
    int row = blockIdx.x * 8 + (threadIdx.x >> 5);
    int lane = threadIdx.x & 31;
    if (row >= MROWS) return;
    const float4* hr = (const float4*)(h2 + (size_t)row * H2);
    const float4* w0 = (const float4*)(wlin);
    const float4* w1 = (const float4*)(wlin + H2);
    float a0 = 0.f, a1 = 0.f;
    for (int i = lane; i < H2 / 4; i += 32) {
        float4 hv = hr[i], x0 = w0[i], x1 = w1[i];
        a0 += hv.x * x0.x + hv.y * x0.y + hv.z * x0.z + hv.w * x0.w;
        a1 += hv.x * x1.x + hv.y * x1.y + hv.z * x1.z + hv.w * x1.w;
    }
#pragma unroll
    for (int o = 16; o; o >>= 1) {
        a0 += __shfl_down_sync(0xffffffffu, a0, o);
        a1 += __shfl_down_sync(0xffffffffu, a1, o);
    }
    if (lane == 0) {
        float l0 = a0 + blin[0], l1 = a1 + blin[1];
        float m = fmaxf(l0, l1);
        float e0 = expf(l0 - m), e1 = expf(l1 - m);
        float inv = 1.f / (e0 + e1);
        float p0 = e0 * inv, p1 = e1 * inv;
        g_emis[row * 2] = p0; g_emis[row * 2 + 1] = p1;
        out[MROWS + row * 2] = p0; out[MROWS + row * 2 + 1] = p1;
    }
}

// ------------------- CRF -------------------
__device__ __forceinline__ float lse2(float x, float y) {
    float m = fmaxf(x, y);
    return m + log1pf(expf(fminf(x, y) - m));
}

__global__ void crf_llh_kernel(const int* __restrict__ labels,
                               const float* __restrict__ start,
                               const float* __restrict__ endv,
                               const float* __restrict__ trans,
                               float* __restrict__ out)
{
    int b = threadIdx.x;
    __shared__ float red[BB];
    int mul = g_w64 ? 2 : 1;
    const int* lab = labels + (size_t)b * WW * mul;
    float t00 = trans[0], t01 = trans[1], t10 = trans[2], t11 = trans[3];

    int prev = lab[0];
    float num = start[prev];
    for (int s = 0; s < WW; s++) {
        int tg = lab[s * mul];
        num += g_emis[(b * WW + s) * 2 + tg];
        if (s > 0) num += trans[prev * 2 + tg];
        prev = tg;
    }
    num += endv[prev];

    float a0 = start[0] + g_emis[(b * WW) * 2 + 0];
    float a1 = start[1] + g_emis[(b * WW) * 2 + 1];
    for (int s = 1; s < WW; s++) {
        float e0 = g_emis[(b * WW + s) * 2 + 0];
        float e1 = g_emis[(b * WW + s) * 2 + 1];
        float x0 = lse2(a0 + t00, a1 + t10) + e0;
        float x1 = lse2(a0 + t01, a1 + t11) + e1;
        a0 = x0; a1 = x1;
    }
    float logZ = lse2(a0 + endv[0], a1 + endv[1]);
    red[b] = num - logZ;
    __syncthreads();
    if (b == 0) {
        float sum = 0.f;
        for (int i = 0; i < BB; i++) sum += red[i];
        out[MROWS + MROWS * 2] = -(sum / (float)BB);
    }
}

__global__ void crf_decode_kernel(const float* __restrict__ start,
                                  const float* __restrict__ endv,
                                  const float* __restrict__ trans,
                                  float* __restrict__ out)
{
    int b = threadIdx.x;
    float t00 = trans[0], t01 = trans[1], t10 = trans[2], t11 = trans[3];
    float s0 = start[0] + g_emis[(b * WW) * 2 + 0];
    float s1 = start[1] + g_emis[(b * WW) * 2 + 1];
    for (int s = 1; s < WW; s++) {
        float c00 = s0 + t00, c10 = s1 + t10;   // into tag 0
        float c01 = s0 + t01, c11 = s1 + t11;   // into tag 1
        unsigned char bp0 = (c10 > c00) ? 1 : 0;  // argmax: first max on tie
        unsigned char bp1 = (c11 > c01) ? 1 : 0;
        float e0 = g_emis[(b * WW + s) * 2 + 0];
        float e1 = g_emis[(b * WW + s) * 2 + 1];
        float n0 = fmaxf(c00, c10) + e0;
        float n1 = fmaxf(c01, c11) + e1;
        g_bp[b][s][0] = bp0; g_bp[b][s][1] = bp1;
        s0 = n0; s1 = n1;
    }
    int tag = (s1 + endv[1] > s0 + endv[0]) ? 1 : 0;
    out[b * WW + (WW - 1)] = (float)tag;
    for (int s = WW - 1; s >= 1; s--) {
        tag = (int)g_bp[b][s][tag];
        out[b * WW + (s - 1)] = (float)tag;
    }
}

// ------------------- host launcher -------------------
extern "C" void kernel_launch(void* const* d_in, const int* in_sizes, int n_in,
                              void* d_out, int out_size)
{
    const float* bert      = (const float*)d_in[0];
    const int*   words     = (const int*)d_in[1];
    const int*   labels    = (const int*)d_in[2];
    const float* w_ih_l0   = (const float*)d_in[3];
    const float* w_hh_l0   = (const float*)d_in[4];
    const float* b_l0      = (const float*)d_in[5];
    const float* w_ih_l0r  = (const float*)d_in[6];
    const float* w_hh_l0r  = (const float*)d_in[7];
    const float* b_l0r     = (const float*)d_in[8];
    const float* w_ih_l1   = (const float*)d_in[9];
    const float* w_hh_l1   = (const float*)d_in[10];
    const float* b_l1      = (const float*)d_in[11];
    const float* w_ih_l1r  = (const float*)d_in[12];
    const float* w_hh_l1r  = (const float*)d_in[13];
    const float* b_l1r     = (const float*)d_in[14];
    const float* w_lin     = (const float*)d_in[15];
    const float* b_lin     = (const float*)d_in[16];
    const float* crf_start = (const float*)d_in[17];
    const float* crf_end   = (const float*)d_in[18];
    const float* crf_trans = (const float*)d_in[19];
    float* out = (float*)d_out;

    float *pfeat, *ppre0, *ppre1, *ph1, *ph2;
    cudaGetSymbolAddress((void**)&pfeat, g_feat);
    cudaGetSymbolAddress((void**)&ppre0, g_pre0);
    cudaGetSymbolAddress((void**)&ppre1, g_pre1);
    cudaGetSymbolAddress((void**)&ph1, g_h1);
    cudaGetSymbolAddress((void**)&ph2, g_h2);

    // W 147456 + h-ring 49152 + gates 6144 + c 1536 = 204288 B dynamic
    const int lstm_smem = (48 * DD + 3 * 128 * BB + 48 * BB + 12 * BB) * 4;
    cudaFuncSetAttribute(lstm_persist_kernel,
                         cudaFuncAttributeMaxDynamicSharedMemorySize, lstm_smem);

    detect_kernel<<<1, 256>>>(words);
    firstidx_kernel<<<(MROWS + 255) / 256, 256>>>(words);
    gather_kernel<<<MROWS, 192>>>(bert);

    dim3 gemm_grid(GG / BN, (MROWS + BM - 1) / BM);
    gemm_bias_kernel<<<gemm_grid, 256>>>(pfeat, w_ih_l0,  b_l0,  ppre0, MROWS, GG, DD);
    gemm_bias_kernel<<<gemm_grid, 256>>>(pfeat, w_ih_l0r, b_l0r, ppre1, MROWS, GG, DD);

    lstm_persist_kernel<<<128, 256, lstm_smem>>>(ppre0, ppre1, w_hh_l0, w_hh_l0r, ph1);

    gemm_bias_kernel<<<gemm_grid, 256>>>(ph1, w_ih_l1,  b_l1,  ppre0, MROWS, GG, H2);
    gemm_bias_kernel<<<gemm_grid, 256>>>(ph1, w_ih_l1r, b_l1r, ppre1, MROWS, GG, H2);

    lstm_persist_kernel<<<128, 256, lstm_smem>>>(ppre0, ppre1, w_hh_l1, w_hh_l1r, ph2);

    emis_kernel<<<MROWS / 8, 256>>>(ph2, w_lin, b_lin, out);
    crf_llh_kernel<<<1, BB>>>(labels, crf_start, crf_end, crf_trans, out);
    crf_decode_kernel<<<1, BB>>>(crf_start, crf_end, crf_trans, out);
}

// round 7
// speedup vs baseline: 1.0217x; 1.0217x over previous
#include <cuda_runtime.h>
#include <cuda_bf16.h>
#include <math.h>
#include <stdint.h>

// Problem constants
#define BB 32
#define TT 512
#define WW 250
#define DD 768
#define GG 3072       // 4*D
#define MROWS 8000    // B*W
#define H2 1536       // 2*D

// ------------------- device scratch (static globals; no allocs) -------------------
__device__ float g_feat[MROWS * DD];
__device__ float g_pre0[MROWS * GG];
__device__ float g_pre1[MROWS * GG];
__device__ float g_h1[MROWS * H2];
__device__ float g_h2[MROWS * H2];
__device__ float g_emis[MROWS * 2];
__device__ float g_hT[2][2][DD][BB];       // [parity][dir][k][b]
__device__ float g_wp0[GG * H2];           // permuted w_ih scratch (fwd)
__device__ float g_wp1[GG * H2];           // permuted w_ih scratch (rev)
__device__ float g_bpm0[GG];
__device__ float g_bpm1[GG];
__device__ int   g_first[MROWS];
__device__ unsigned char g_bp[BB][WW][2];
__device__ unsigned g_cnt[2] = {0, 0};
__device__ unsigned g_gen[2] = {0, 0};
__device__ int g_w64 = 0;

// ------------------- packed f32x2 helpers -------------------
typedef unsigned long long ull;
__device__ __forceinline__ ull fma2(ull a, ull b, ull c) {
    ull d;
    asm("fma.rn.f32x2 %0, %1, %2, %3;" : "=l"(d) : "l"(a), "l"(b), "l"(c));
    return d;
}
__device__ __forceinline__ ull packf2(float lo, float hi) {
    ull d;
    asm("mov.b64 %0, {%1, %2};" : "=l"(d)
        : "r"(__float_as_uint(lo)), "r"(__float_as_uint(hi)));
    return d;
}
__device__ __forceinline__ float2 unpackf2(ull v) {
    unsigned lo, hi;
    asm("mov.b64 {%0, %1}, %2;" : "=r"(lo), "=r"(hi) : "l"(v));
    return make_float2(__uint_as_float(lo), __uint_as_float(hi));
}

// ------------------- int64 vs int32 detection -------------------
__global__ void detect_kernel(const int* __restrict__ w) {
    __shared__ int bad;
    if (threadIdx.x == 0) bad = 0;
    __syncthreads();
    for (int i = threadIdx.x; i < 8192; i += blockDim.x) {
        int v = w[2 * i + 1];
        if (v != 0 && v != -1) bad = 1;
    }
    __syncthreads();
    if (threadIdx.x == 0) g_w64 = bad ? 0 : 1;
}

// ------------------- first-subtoken index -------------------
__global__ void firstidx_kernel(const int* __restrict__ w) {
    int id = blockIdx.x * blockDim.x + threadIdx.x;
    if (id >= MROWS) return;
    int b = id / WW, ww = id % WW;
    int mul = g_w64 ? 2 : 1;
    const int* row = w + (size_t)b * TT * mul;
    int idx = TT - 1;
    for (int t = 0; t < TT; t++) {
        if (row[t * mul] == ww) { idx = t; break; }
    }
    g_first[id] = idx;
}

// ------------------- gather feat rows -------------------
__global__ void gather_kernel(const float* __restrict__ bert) {
    int row = blockIdx.x;
    int fi = g_first[row];
    int b = row / WW;
    const float4* src = (const float4*)(bert + ((size_t)b * TT + fi) * DD);
    float4* dst = (float4*)(g_feat + (size_t)row * DD);
    for (int i = threadIdx.x; i < DD / 4; i += blockDim.x) dst[i] = src[i];
}

// ------------------- weight/bias row permutation -------------------
// dst row n' = c*48 + g*12 + u  <-  src row g*768 + c*12 + u
__global__ void permute_kernel(const float* __restrict__ src_w,
                               const float* __restrict__ src_b,
                               float* __restrict__ dst_w,
                               float* __restrict__ dst_b, int K)
{
    int np = blockIdx.x;
    int c = np / 48, r = np % 48;
    int g = r / 12, u = r % 12;
    int srow = g * DD + c * 12 + u;
    const float4* s = (const float4*)(src_w + (size_t)srow * K);
    float4* d = (float4*)(dst_w + (size_t)np * K);
    for (int i = threadIdx.x; i < K / 4; i += blockDim.x) d[i] = s[i];
    if (threadIdx.x == 0) dst_b[np] = src_b[srow];
}

// ------------------- fp32 GEMM (FMA2): C[m][n]=sum_k A[m][k]*B[n][k]+bias[n] -------------------
#define BM 128
#define BN 128
#define BKK 8
__global__ __launch_bounds__(256) void gemm_bias_kernel(
    const float* __restrict__ A, const float* __restrict__ B,
    const float* __restrict__ bias, float* __restrict__ C,
    int M, int N, int K)
{
    __shared__ float As[2][BKK][BM];
    __shared__ float Bs[2][BKK][BN];
    int tid = threadIdx.x;
    int m0 = blockIdx.y * BM;
    int n0 = blockIdx.x * BN;

    int lr = tid >> 1;
    int lk = (tid & 1) * 4;
    int ty = tid >> 4;
    int tx = tid & 15;

    ull acc2[8][4];
#pragma unroll
    for (int r = 0; r < 8; r++)
#pragma unroll
        for (int c = 0; c < 4; c++) acc2[r][c] = 0ull;

    int nIter = K / BKK;
    float4 aReg, bReg;

    {
        int m = m0 + lr;
        aReg = (m < M) ? *(const float4*)(A + (size_t)m * K + lk)
                       : make_float4(0.f, 0.f, 0.f, 0.f);
        bReg = *(const float4*)(B + (size_t)(n0 + lr) * K + lk);
        As[0][lk + 0][lr] = aReg.x; As[0][lk + 1][lr] = aReg.y;
        As[0][lk + 2][lr] = aReg.z; As[0][lk + 3][lr] = aReg.w;
        Bs[0][lk + 0][lr] = bReg.x; Bs[0][lk + 1][lr] = bReg.y;
        Bs[0][lk + 2][lr] = bReg.z; Bs[0][lk + 3][lr] = bReg.w;
    }
    __syncthreads();

    int cur = 0;
    for (int it = 0; it < nIter; ++it) {
        if (it + 1 < nIter) {
            int k0 = (it + 1) * BKK;
            int m = m0 + lr;
            aReg = (m < M) ? *(const float4*)(A + (size_t)m * K + k0 + lk)
                           : make_float4(0.f, 0.f, 0.f, 0.f);
            bReg = *(const float4*)(B + (size_t)(n0 + lr) * K + k0 + lk);
        }
#pragma unroll
        for (int k = 0; k < BKK; k++) {
            float a_[8];
            *(float4*)&a_[0] = *(const float4*)&As[cur][k][ty * 8];
            *(float4*)&a_[4] = *(const float4*)&As[cur][k][ty * 8 + 4];
            ulonglong2 bl0 = *(const ulonglong2*)&Bs[cur][k][tx * 8];
            ulonglong2 bl1 = *(const ulonglong2*)&Bs[cur][k][tx * 8 + 4];
            ull b2[4] = {bl0.x, bl0.y, bl1.x, bl1.y};
#pragma unroll
            for (int r = 0; r < 8; r++) {
                ull a2 = packf2(a_[r], a_[r]);
#pragma unroll
                for (int c = 0; c < 4; c++)
                    acc2[r][c] = fma2(a2, b2[c], acc2[r][c]);
            }
        }
        if (it + 1 < nIter) {
            cur ^= 1;
            As[cur][lk + 0][lr] = aReg.x; As[cur][lk + 1][lr] = aReg.y;
            As[cur][lk + 2][lr] = aReg.z; As[cur][lk + 3][lr] = aReg.w;
            Bs[cur][lk + 0][lr] = bReg.x; Bs[cur][lk + 1][lr] = bReg.y;
            Bs[cur][lk + 2][lr] = bReg.z; Bs[cur][lk + 3][lr] = bReg.w;
            __syncthreads();
        }
    }

#pragma unroll
    for (int r = 0; r < 8; r++) {
        int m = m0 + ty * 8 + r;
        if (m < M) {
#pragma unroll
            for (int c = 0; c < 4; c++) {
                int n = n0 + tx * 8 + 2 * c;
                float2 v = unpackf2(acc2[r][c]);
                C[(size_t)m * N + n]     = v.x + bias[n];
                C[(size_t)m * N + n + 1] = v.y + bias[n + 1];
            }
        }
    }
}

// ------------------- TMA / mbarrier helpers -------------------
__device__ __forceinline__ uint32_t smem_u32(const void* p) {
    uint32_t a;
    asm("{ .reg .u64 t; cvta.to.shared.u64 t, %1; cvt.u32.u64 %0, t; }"
        : "=r"(a) : "l"(p));
    return a;
}
__device__ __forceinline__ void mbar_init(uint32_t addr, uint32_t count) {
    asm volatile("mbarrier.init.shared.b64 [%0], %1;" :: "r"(addr), "r"(count) : "memory");
}
__device__ __forceinline__ void mbar_wait(uint32_t addr, uint32_t phase) {
    uint32_t done;
    do {
        asm volatile(
            "{\n\t.reg .pred p;\n\t"
            "mbarrier.try_wait.parity.acquire.cta.shared::cta.b64 p, [%1], %2, 0x989680;\n\t"
            "selp.b32 %0, 1, 0, p;\n\t}"
            : "=r"(done) : "r"(addr), "r"(phase) : "memory");
    } while (!done);
}
__device__ __forceinline__ void mbar_expect(uint32_t mbar, uint32_t bytes) {
    asm volatile("mbarrier.arrive.expect_tx.shared.b64 _, [%0], %1;"
                 :: "r"(mbar), "r"(bytes) : "memory");
}
__device__ __forceinline__ void bulk_cp(uint32_t mbar, uint32_t dst_smem,
                                        const void* src_gmem, uint32_t bytes) {
    asm volatile(
        "cp.async.bulk.shared::cluster.global.mbarrier::complete_tx::bytes "
        "[%0], [%1], %2, [%3];"
        :: "r"(dst_smem), "l"(src_gmem), "r"(bytes), "r"(mbar) : "memory");
}

// ------------------- persistent LSTM layer kernel -------------------
#define NCTA_DIR 64
#define HCHUNK_BYTES (128 * BB * 4)   // 16384 B
#define PRE_SLICE_B (48 * BB * 4)     // 6144 B per step per CTA

__device__ __forceinline__ void dir_barrier(int dir) {
    __threadfence();
    __syncthreads();
    if (threadIdx.x == 0) {
        unsigned my = *(volatile unsigned*)&g_gen[dir];
        unsigned t = atomicAdd(&g_cnt[dir], 1u);
        if (t == NCTA_DIR - 1) {
            g_cnt[dir] = 0;
            __threadfence();
            atomicAdd(&g_gen[dir], 1u);
        } else {
            while (*(volatile unsigned*)&g_gen[dir] == my) { __nanosleep(64); }
            __threadfence();
        }
    }
    __syncthreads();
}

__global__ __launch_bounds__(256) void lstm_persist_kernel(
    const float* __restrict__ preF, const float* __restrict__ preR,
    const float* __restrict__ whhF, const float* __restrict__ whhR,
    float* __restrict__ hout)
{
    extern __shared__ float sm[];
    float* w2_s   = sm;                      // 48*768 interleaved row-pairs = 36864
    float* h_s    = w2_s + 48 * DD;          // 3*128*32 = 12288
    float* gate_s = h_s + 3 * 128 * BB;      // 32*48 = 1536  [b][r]
    float* c_s    = gate_s + 32 * 48;        // 384           [b*12+u]
    float* pre_s  = c_s + 384;               // 2*1536 = 3072 [slot][b*48+r]
    __shared__ __align__(8) unsigned long long mbar_arr[5];

    int tid = threadIdx.x, bid = blockIdx.x;
    int dir = bid >> 6;
    int cta = bid & 63;
    int U0 = cta * 12;
    const float* whh = dir ? whhR : whhF;
    const float* pre = dir ? preR : preF;

    int warp = tid >> 5, lane = tid & 31;
    int r0 = warp * 6;        // gate rows r0..r0+5
    int p0 = warp * 3;        // row-pairs

    uint32_t mbar0 = smem_u32(&mbar_arr[0]);
    uint32_t hsm0  = smem_u32(h_s);
    uint32_t psm0  = smem_u32(pre_s);

    if (tid == 0) {
        for (int i = 0; i < 5; i++) mbar_init(mbar0 + i * 8, 1);
        // prefetch pre slice for s=0 into slot 0
        int t0 = dir ? (WW - 1) : 0;
        mbar_expect(mbar0 + 3 * 8, PRE_SLICE_B);
        for (int b = 0; b < BB; b++)
            bulk_cp(mbar0 + 3 * 8, psm0 + b * 192,
                    pre + ((size_t)b * WW + t0) * GG + cta * 48, 192);
    }

    // One-time W load, interleaved by row pair: w2_s[(r>>1)*1536 + k*2 + (r&1)]
    for (int idx = tid; idx < 48 * (DD / 4); idx += 256) {
        int r = idx / (DD / 4), k4 = idx % (DD / 4);
        int g = r / 12, u = r % 12;
        float4 v = *(const float4*)(whh + ((size_t)(g * DD + U0 + u)) * DD + k4 * 4);
        float* base = &w2_s[(r >> 1) * (2 * DD) + (k4 * 4) * 2 + (r & 1)];
        base[0] = v.x; base[2] = v.y; base[4] = v.z; base[6] = v.w;
    }
    for (int idx = tid; idx < 12 * BB; idx += 256) c_s[idx] = 0.f;
    __syncthreads();

    uint32_t phbits = 0;    // h-slot phases (bits 0..2)
    uint32_t preph = 0;     // pre-slot phases (bits 0..1)

    for (int s = 0; s < WW; ++s) {
        int t = dir ? (WW - 1 - s) : s;

        // prefetch next step's pre slice
        if (tid == 0 && s + 1 < WW) {
            int tn = dir ? (WW - 2 - s) : (s + 1);
            int slot = (s + 1) & 1;
            mbar_expect(mbar0 + (3 + slot) * 8, PRE_SLICE_B);
            for (int b = 0; b < BB; b++)
                bulk_cp(mbar0 + (3 + slot) * 8, psm0 + slot * PRE_SLICE_B + b * 192,
                        pre + ((size_t)b * WW + tn) * GG + cta * 48, 192);
        }

        ull acc2[3] = {0ull, 0ull, 0ull};

        if (s > 0) {
            const char* hsrc = (const char*)&g_hT[(s - 1) & 1][dir][0][0];
            if (tid == 0) {
                asm volatile("fence.proxy.async;" ::: "memory");
                mbar_expect(mbar0 + 0, HCHUNK_BYTES);
                bulk_cp(mbar0 + 0, hsm0 + 0 * HCHUNK_BYTES, hsrc + 0 * HCHUNK_BYTES, HCHUNK_BYTES);
                mbar_expect(mbar0 + 8, HCHUNK_BYTES);
                bulk_cp(mbar0 + 8, hsm0 + 1 * HCHUNK_BYTES, hsrc + 1 * HCHUNK_BYTES, HCHUNK_BYTES);
            }
#pragma unroll 1
            for (int c = 0; c < 6; c++) {
                int slot = c % 3;
                mbar_wait(mbar0 + slot * 8, (phbits >> slot) & 1u);
                phbits ^= (1u << slot);
                __syncthreads();   // chunk c-1 consumers done -> safe to refill its slot
                if (tid == 0 && c < 4) {
                    int s2 = (c + 2) % 3;
                    mbar_expect(mbar0 + s2 * 8, HCHUNK_BYTES);
                    bulk_cp(mbar0 + s2 * 8, hsm0 + s2 * HCHUNK_BYTES,
                            hsrc + (size_t)(c + 2) * HCHUNK_BYTES, HCHUNK_BYTES);
                }
                const float* hb = h_s + slot * (128 * BB);
#pragma unroll 4
                for (int kk = 0; kk < 128; kk += 4) {
                    float h0 = hb[(kk + 0) * BB + lane];
                    float h1 = hb[(kk + 1) * BB + lane];
                    float h2v = hb[(kk + 2) * BB + lane];
                    float h3 = hb[(kk + 3) * BB + lane];
                    ull hp0 = packf2(h0, h0), hp1 = packf2(h1, h1);
                    ull hp2 = packf2(h2v, h2v), hp3 = packf2(h3, h3);
#pragma unroll
                    for (int j2 = 0; j2 < 3; j2++) {
                        const float* wb = &w2_s[(p0 + j2) * (2 * DD) + (c * 128 + kk) * 2];
                        ulonglong2 wv0 = *(const ulonglong2*)(wb);
                        ulonglong2 wv1 = *(const ulonglong2*)(wb + 4);
                        acc2[j2] = fma2(wv0.x, hp0, acc2[j2]);
                        acc2[j2] = fma2(wv0.y, hp1, acc2[j2]);
                        acc2[j2] = fma2(wv1.x, hp2, acc2[j2]);
                        acc2[j2] = fma2(wv1.y, hp3, acc2[j2]);
                    }
                }
            }
        }

        // publish gate partials: gate_s[b][r]
#pragma unroll
        for (int j2 = 0; j2 < 3; j2++) {
            float2 v = unpackf2(acc2[j2]);
            gate_s[lane * 48 + r0 + 2 * j2]     = v.x;
            gate_s[lane * 48 + r0 + 2 * j2 + 1] = v.y;
        }
        // wait for this step's pre slice
        {
            int slot = s & 1;
            mbar_wait(mbar0 + (3 + slot) * 8, (preph >> slot) & 1u);
            preph ^= (1u << slot);
        }
        __syncthreads();

        // elementwise LSTM cell: 384 items (b*12+u)
        const float* ps = pre_s + (s & 1) * (48 * BB);
        for (int item = tid; item < 12 * BB; item += 256) {
            int b = item / 12, u = item % 12;
            float gi = ps[b * 48 + 0 * 12 + u] + gate_s[b * 48 + 0 * 12 + u];
            float gf = ps[b * 48 + 1 * 12 + u] + gate_s[b * 48 + 1 * 12 + u];
            float gg = ps[b * 48 + 2 * 12 + u] + gate_s[b * 48 + 2 * 12 + u];
            float go = ps[b * 48 + 3 * 12 + u] + gate_s[b * 48 + 3 * 12 + u];
            float iv = 1.f / (1.f + expf(-gi));
            float fv = 1.f / (1.f + expf(-gf));
            float gv = tanhf(gg);
            float ov = 1.f / (1.f + expf(-go));
            float cc = fv * c_s[item] + iv * gv;
            c_s[item] = cc;
            float hh = ov * tanhf(cc);
            __stcg(&g_hT[s & 1][dir][U0 + u][b], hh);
            hout[((size_t)(b * WW + t)) * H2 + dir * DD + U0 + u] = hh;
        }

        if (s < WW - 1) dir_barrier(dir);
    }
}

// ------------------- emissions: linear (NT=2) + softmax -------------------
__global__ void emis_kernel(const float* __restrict__ h2,
                            const float* __restrict__ wlin,
                            const float* __restrict__ blin,
                            float* __restrict__ out)
{
    int row = blockIdx.x * 8 + (threadIdx.x >> 5);
    int lane = threadIdx.x & 31;
    if (row >= MROWS) return;
    const float4* hr = (const float4*)(h2 + (size_t)row * H2);
    const float4* w0 = (const float4*)(wlin);
    const float4* w1 = (const float4*)(wlin + H2);
    float a0 = 0.f, a1 = 0.f;
    for (int i = lane; i < H2 / 4; i += 32) {
        float4 hv = hr[i], x0 = w0[i], x1 = w1[i];
        a0 += hv.x * x0.x + hv.y * x0.y + hv.z * x0.z + hv.w * x0.w;
        a1 += hv.x * x1.x + hv.y * x1.y + hv.z * x1.z + hv.w * x1.w;
    }
#pragma unroll
    for (int o = 16; o; o >>= 1) {
        a0 += __shfl_down_sync(0xffffffffu, a0, o);
        a1 += __shfl_down_sync(0xffffffffu, a1, o);
    }
    if (lane == 0) {
        float l0 = a0 + blin[0], l1 = a1 + blin[1];
        float m = fmaxf(l0, l1);
        float e0 = expf(l0 - m), e1 = expf(l1 - m);
        float inv = 1.f / (e0 + e1);
        float p0 = e0 * inv, p1 = e1 * inv;
        g_emis[row * 2] = p0; g_emis[row * 2 + 1] = p1;
        out[MROWS + row * 2] = p0; out[MROWS + row * 2 + 1] = p1;
    }
}

// ------------------- CRF -------------------
__device__ __forceinline__ float lse2(float x, float y) {
    float m = fmaxf(x, y);
    return m + log1pf(expf(fminf(x, y) - m));
}

__global__ void crf_llh_kernel(const int* __restrict__ labels,
                               const float* __restrict__ start,
                               const float* __restrict__ endv,
                               const float* __restrict__ trans,
                               float* __restrict__ out)
{
    int b = threadIdx.x;
    __shared__ float red[BB];
    int mul = g_w64 ? 2 : 1;
    const int* lab = labels + (size_t)b * WW * mul;
    float t00 = trans[0], t01 = trans[1], t10 = trans[2], t11 = trans[3];

    int prev = lab[0];
    float num = start[prev];
    for (int s = 0; s < WW; s++) {
        int tg = lab[s * mul];
        num += g_emis[(b * WW + s) * 2 + tg];
        if (s > 0) num += trans[prev * 2 + tg];
        prev = tg;
    }
    num += endv[prev];

    float a0 = start[0] + g_emis[(b * WW) * 2 + 0];
    float a1 = start[1] + g_emis[(b * WW) * 2 + 1];
    for (int s = 1; s < WW; s++) {
        float e0 = g_emis[(b * WW + s) * 2 + 0];
        float e1 = g_emis[(b * WW + s) * 2 + 1];
        float x0 = lse2(a0 + t00, a1 + t10) + e0;
        float x1 = lse2(a0 + t01, a1 + t11) + e1;
        a0 = x0; a1 = x1;
    }
    float logZ = lse2(a0 + endv[0], a1 + endv[1]);
    red[b] = num - logZ;
    __syncthreads();
    if (b == 0) {
        float sum = 0.f;
        for (int i = 0; i < BB; i++) sum += red[i];
        out[MROWS + MROWS * 2] = -(sum / (float)BB);
    }
}

__global__ void crf_decode_kernel(const float* __restrict__ start,
                                  const float* __restrict__ endv,
                                  const float* __restrict__ trans,
                                  float* __restrict__ out)
{
    int b = threadIdx.x;
    float t00 = trans[0], t01 = trans[1], t10 = trans[2], t11 = trans[3];
    float s0 = start[0] + g_emis[(b * WW) * 2 + 0];
    float s1 = start[1] + g_emis[(b * WW) * 2 + 1];
    for (int s = 1; s < WW; s++) {
        float c00 = s0 + t00, c10 = s1 + t10;
        float c01 = s0 + t01, c11 = s1 + t11;
        unsigned char bp0 = (c10 > c00) ? 1 : 0;
        unsigned char bp1 = (c11 > c01) ? 1 : 0;
        float e0 = g_emis[(b * WW + s) * 2 + 0];
        float e1 = g_emis[(b * WW + s) * 2 + 1];
        float n0 = fmaxf(c00, c10) + e0;
        float n1 = fmaxf(c01, c11) + e1;
        g_bp[b][s][0] = bp0; g_bp[b][s][1] = bp1;
        s0 = n0; s1 = n1;
    }
    int tag = (s1 + endv[1] > s0 + endv[0]) ? 1 : 0;
    out[b * WW + (WW - 1)] = (float)tag;
    for (int s = WW - 1; s >= 1; s--) {
        tag = (int)g_bp[b][s][tag];
        out[b * WW + (s - 1)] = (float)tag;
    }
}

// ------------------- host launcher -------------------
extern "C" void kernel_launch(void* const* d_in, const int* in_sizes, int n_in,
                              void* d_out, int out_size)
{
    const float* bert      = (const float*)d_in[0];
    const int*   words     = (const int*)d_in[1];
    const int*   labels    = (const int*)d_in[2];
    const float* w_ih_l0   = (const float*)d_in[3];
    const float* w_hh_l0   = (const float*)d_in[4];
    const float* b_l0      = (const float*)d_in[5];
    const float* w_ih_l0r  = (const float*)d_in[6];
    const float* w_hh_l0r  = (const float*)d_in[7];
    const float* b_l0r     = (const float*)d_in[8];
    const float* w_ih_l1   = (const float*)d_in[9];
    const float* w_hh_l1   = (const float*)d_in[10];
    const float* b_l1      = (const float*)d_in[11];
    const float* w_ih_l1r  = (const float*)d_in[12];
    const float* w_hh_l1r  = (const float*)d_in[13];
    const float* b_l1r     = (const float*)d_in[14];
    const float* w_lin     = (const float*)d_in[15];
    const float* b_lin     = (const float*)d_in[16];
    const float* crf_start = (const float*)d_in[17];
    const float* crf_end   = (const float*)d_in[18];
    const float* crf_trans = (const float*)d_in[19];
    float* out = (float*)d_out;

    float *pfeat, *ppre0, *ppre1, *ph1, *ph2, *pwp0, *pwp1, *pbp0, *pbp1;
    cudaGetSymbolAddress((void**)&pfeat, g_feat);
    cudaGetSymbolAddress((void**)&ppre0, g_pre0);
    cudaGetSymbolAddress((void**)&ppre1, g_pre1);
    cudaGetSymbolAddress((void**)&ph1, g_h1);
    cudaGetSymbolAddress((void**)&ph2, g_h2);
    cudaGetSymbolAddress((void**)&pwp0, g_wp0);
    cudaGetSymbolAddress((void**)&pwp1, g_wp1);
    cudaGetSymbolAddress((void**)&pbp0, g_bpm0);
    cudaGetSymbolAddress((void**)&pbp1, g_bpm1);

    // W 147456 + h ring 49152 + gate 6144 + c 1536 + pre 12288 = 216576 B
    const int lstm_smem = (48 * DD + 3 * 128 * BB + 32 * 48 + 384 + 2 * 48 * BB) * 4;
    cudaFuncSetAttribute(lstm_persist_kernel,
                         cudaFuncAttributeMaxDynamicSharedMemorySize, lstm_smem);

    detect_kernel<<<1, 256>>>(words);
    firstidx_kernel<<<(MROWS + 255) / 256, 256>>>(words);
    gather_kernel<<<MROWS, 192>>>(bert);

    dim3 gemm_grid(GG / BN, (MROWS + BM - 1) / BM);

    permute_kernel<<<GG, 128>>>(w_ih_l0,  b_l0,  pwp0, pbp0, DD);
    permute_kernel<<<GG, 128>>>(w_ih_l0r, b_l0r, pwp1, pbp1, DD);
    gemm_bias_kernel<<<gemm_grid, 256>>>(pfeat, pwp0, pbp0, ppre0, MROWS, GG, DD);
    gemm_bias_kernel<<<gemm_grid, 256>>>(pfeat, pwp1, pbp1, ppre1, MROWS, GG, DD);

    lstm_persist_kernel<<<128, 256, lstm_smem>>>(ppre0, ppre1, w_hh_l0, w_hh_l0r, ph1);

    permute_kernel<<<GG, 128>>>(w_ih_l1,  b_l1,  pwp0, pbp0, H2);
    permute_kernel<<<GG, 128>>>(w_ih_l1r, b_l1r, pwp1, pbp1, H2);
    gemm_bias_kernel<<<gemm_grid, 256>>>(ph1, pwp0, pbp0, ppre0, MROWS, GG, H2);
    gemm_bias_kernel<<<gemm_grid, 256>>>(ph1, pwp1, pbp1, ppre1, MROWS, GG, H2);

    lstm_persist_kernel<<<128, 256, lstm_smem>>>(ppre0, ppre1, w_hh_l1, w_hh_l1r, ph2);

    emis_kernel<<<MROWS / 8, 256>>>(ph2, w_lin, b_lin, out);
    crf_llh_kernel<<<1, BB>>>(labels, crf_start, crf_end, crf_trans, out);
    crf_decode_kernel<<<1, BB>>>(crf_start, crf_end, crf_trans, out);
}

// round 8
// speedup vs baseline: 1.0666x; 1.0440x over previous
#include <cuda_runtime.h>
#include <cuda_bf16.h>
#include <math.h>
#include <stdint.h>

// Problem constants
#define BB 32
#define TT 512
#define WW 250
#define DD 768
#define GG 3072       // 4*D
#define MROWS 8000    // B*W
#define H2 1536       // 2*D
#define MP 8064       // padded M (63*128)

// ------------------- device scratch (static globals; no allocs) -------------------
__device__ float g_feat[MROWS * DD];
__device__ float g_pre0[MROWS * GG];
__device__ float g_pre1[MROWS * GG];
__device__ float g_h1[MROWS * H2];
__device__ float g_h2[MROWS * H2];
__device__ float g_emis[MROWS * 2];
__device__ float g_hT[2][2][DD][BB];       // [parity][dir][k][b]
__device__ float g_a3[3 * H2 * MP];        // split-transposed A: [k'][m]
__device__ float g_b3f[3 * H2 * GG];       // split-transposed permuted W (fwd)
__device__ float g_b3r[3 * H2 * GG];       // (rev)
__device__ float g_bpm0[GG];
__device__ float g_bpm1[GG];
__device__ int   g_first[MROWS];
__device__ unsigned char g_bp[BB][WW][2];
__device__ unsigned g_cnt[2] = {0, 0};
__device__ unsigned g_gen[2] = {0, 0};
__device__ int g_w64 = 0;

// ------------------- packed f32x2 helpers (LSTM) -------------------
typedef unsigned long long ull;
__device__ __forceinline__ ull fma2(ull a, ull b, ull c) {
    ull d;
    asm("fma.rn.f32x2 %0, %1, %2, %3;" : "=l"(d) : "l"(a), "l"(b), "l"(c));
    return d;
}
__device__ __forceinline__ ull packf2(float lo, float hi) {
    ull d;
    asm("mov.b64 %0, {%1, %2};" : "=l"(d)
        : "r"(__float_as_uint(lo)), "r"(__float_as_uint(hi)));
    return d;
}
__device__ __forceinline__ float2 unpackf2(ull v) {
    unsigned lo, hi;
    asm("mov.b64 {%0, %1}, %2;" : "=r"(lo), "=r"(hi) : "l"(v));
    return make_float2(__uint_as_float(lo), __uint_as_float(hi));
}

// ------------------- tf32 helpers -------------------
__device__ __forceinline__ float to_tf32(float v) {
    float r;
    asm("cvt.rna.tf32.f32 %0, %1;" : "=f"(r) : "f"(v));
    return r;
}

// ------------------- int64 vs int32 detection -------------------
__global__ void detect_kernel(const int* __restrict__ w) {
    __shared__ int bad;
    if (threadIdx.x == 0) bad = 0;
    __syncthreads();
    for (int i = threadIdx.x; i < 8192; i += blockDim.x) {
        int v = w[2 * i + 1];
        if (v != 0 && v != -1) bad = 1;
    }
    __syncthreads();
    if (threadIdx.x == 0) g_w64 = bad ? 0 : 1;
}

// ------------------- first-subtoken index -------------------
__global__ void firstidx_kernel(const int* __restrict__ w) {
    int id = blockIdx.x * blockDim.x + threadIdx.x;
    if (id >= MROWS) return;
    int b = id / WW, ww = id % WW;
    int mul = g_w64 ? 2 : 1;
    const int* row = w + (size_t)b * TT * mul;
    int idx = TT - 1;
    for (int t = 0; t < TT; t++) {
        if (row[t * mul] == ww) { idx = t; break; }
    }
    g_first[id] = idx;
}

// ------------------- gather feat rows -------------------
__global__ void gather_kernel(const float* __restrict__ bert) {
    int row = blockIdx.x;
    int fi = g_first[row];
    int b = row / WW;
    const float4* src = (const float4*)(bert + ((size_t)b * TT + fi) * DD);
    float4* dst = (float4*)(g_feat + (size_t)row * DD);
    for (int i = threadIdx.x; i < DD / 4; i += blockDim.x) dst[i] = src[i];
}

// ------------------- split+transpose A: src[M][K] -> dstT[3K][MP] -------------------
// segments: [hi | hi | lo]
__global__ void splitA_kernel(const float* __restrict__ src,
                              float* __restrict__ dstT, int M, int K)
{
    __shared__ float t[32][33];
    int k0 = blockIdx.x * 32, m0 = blockIdx.y * 32;
    int tx = threadIdx.x, ty = threadIdx.y;   // 32 x 8
#pragma unroll
    for (int r = 0; r < 4; r++) {
        int row = m0 + ty + r * 8;
        t[ty + r * 8][tx] = (row < M) ? src[(size_t)row * K + k0 + tx] : 0.f;
    }
    __syncthreads();
#pragma unroll
    for (int r = 0; r < 4; r++) {
        int kl = ty + r * 8;
        int k = k0 + kl;
        float v = t[tx][kl];
        float hi = to_tf32(v);
        float lo = to_tf32(v - hi);
        int m = m0 + tx;
        dstT[(size_t)k * MP + m] = hi;
        dstT[(size_t)(K + k) * MP + m] = hi;
        dstT[(size_t)(2 * K + k) * MP + m] = lo;
    }
}

// ------------------- split+transpose+permute W: w[GG][K] -> dstT[3K][GG] -------------------
// permuted col n' = c*48 + g*12 + u  <-  src row g*768 + c*12 + u
// segments: [hi | lo | hi]
__global__ void splitB_kernel(const float* __restrict__ w,
                              const float* __restrict__ bias,
                              float* __restrict__ dstT,
                              float* __restrict__ dstb, int K)
{
    __shared__ float t[32][33];
    int k0 = blockIdx.x * 32, n0 = blockIdx.y * 32;
    int tx = threadIdx.x, ty = threadIdx.y;
#pragma unroll
    for (int r = 0; r < 4; r++) {
        int np = n0 + ty + r * 8;
        int c = np / 48, rr = np % 48;
        int g = rr / 12, u = rr % 12;
        int srow = g * DD + c * 12 + u;
        t[ty + r * 8][tx] = w[(size_t)srow * K + k0 + tx];
    }
    if (k0 == 0 && ty == 0) {
        int np = n0 + tx;
        int c = np / 48, rr = np % 48;
        int g = rr / 12, u = rr % 12;
        dstb[np] = bias[g * DD + c * 12 + u];
    }
    __syncthreads();
#pragma unroll
    for (int r = 0; r < 4; r++) {
        int kl = ty + r * 8;
        int k = k0 + kl;
        float v = t[tx][kl];
        float hi = to_tf32(v);
        float lo = to_tf32(v - hi);
        int n = n0 + tx;
        dstT[(size_t)k * GG + n] = hi;
        dstT[(size_t)(K + k) * GG + n] = lo;
        dstT[(size_t)(2 * K + k) * GG + n] = hi;
    }
}

// ------------------- tf32 tensor-core GEMM -------------------
// C[m][n] = sum_k' AT[k'][m] * BT[k'][n] + bias[n]
// 128x128 CTA tile, BK=32, 8 warps (64x32 warp tiles), XOR-swizzled smem.
#define GBK 32
__global__ __launch_bounds__(256) void mma_gemm_kernel(
    const float* __restrict__ AT, const float* __restrict__ BT,
    const float* __restrict__ bias, float* __restrict__ C,
    int M, int K3)
{
    extern __shared__ float gsm[];
    float* As = gsm;                 // 2 x 32 x 128
    float* Bs = gsm + 2 * GBK * 128; // 2 x 32 x 128

    int tid = threadIdx.x;
    int warp = tid >> 5, lane = tid & 31;
    int n0 = blockIdx.x * 128;
    int m0 = blockIdx.y * 128;

    int warp_m = (warp >> 2) * 64;
    int warp_n = (warp & 3) * 32;
    int gid = lane >> 2, tig = lane & 3;
    int mask = tig << 3;

    float d[4][4][4];
#pragma unroll
    for (int i = 0; i < 4; i++)
#pragma unroll
        for (int j = 0; j < 4; j++)
#pragma unroll
            for (int q = 0; q < 4; q++) d[i][j][q] = 0.f;

    int nIter = K3 / GBK;

    // stage iter 0 into buffer 0
    {
#pragma unroll
        for (int jj = 0; jj < 4; jj++) {
            int r = warp * 4 + jj;
            float4 av = *(const float4*)(AT + (size_t)r * MP + m0 + lane * 4);
            float4 bv = *(const float4*)(BT + (size_t)r * GG + n0 + lane * 4);
            *(float4*)&As[r * 128 + ((lane * 4) ^ ((r & 3) << 3))] = av;
            *(float4*)&Bs[r * 128 + ((lane * 4) ^ ((r & 3) << 3))] = bv;
        }
    }
    __syncthreads();

    int buf = 0;
    for (int it = 0; it < nIter; ++it) {
        float4 aR[4], bR[4];
        if (it + 1 < nIter) {
            size_t kbase = (size_t)(it + 1) * GBK;
#pragma unroll
            for (int jj = 0; jj < 4; jj++) {
                int r = warp * 4 + jj;
                aR[jj] = *(const float4*)(AT + (kbase + r) * MP + m0 + lane * 4);
                bR[jj] = *(const float4*)(BT + (kbase + r) * GG + n0 + lane * 4);
            }
        }

        const float* Ab = As + buf * (GBK * 128);
        const float* Bb = Bs + buf * (GBK * 128);
#pragma unroll
        for (int kk = 0; kk < GBK; kk += 8) {
            int row0 = kk + tig, row1 = kk + tig + 4;
            unsigned a[4][4], b[4][2];
#pragma unroll
            for (int i = 0; i < 4; i++) {
                int mi = warp_m + i * 16 + gid;
                a[i][0] = __float_as_uint(Ab[row0 * 128 + (mi ^ mask)]);
                a[i][1] = __float_as_uint(Ab[row0 * 128 + ((mi + 8) ^ mask)]);
                a[i][2] = __float_as_uint(Ab[row1 * 128 + (mi ^ mask)]);
                a[i][3] = __float_as_uint(Ab[row1 * 128 + ((mi + 8) ^ mask)]);
            }
#pragma unroll
            for (int j = 0; j < 4; j++) {
                int nj = warp_n + j * 8 + gid;
                b[j][0] = __float_as_uint(Bb[row0 * 128 + (nj ^ mask)]);
                b[j][1] = __float_as_uint(Bb[row1 * 128 + (nj ^ mask)]);
            }
#pragma unroll
            for (int i = 0; i < 4; i++)
#pragma unroll
                for (int j = 0; j < 4; j++) {
                    asm("mma.sync.aligned.m16n8k8.row.col.f32.tf32.tf32.f32 "
                        "{%0,%1,%2,%3}, {%4,%5,%6,%7}, {%8,%9}, {%0,%1,%2,%3};"
                        : "+f"(d[i][j][0]), "+f"(d[i][j][1]),
                          "+f"(d[i][j][2]), "+f"(d[i][j][3])
                        : "r"(a[i][0]), "r"(a[i][1]), "r"(a[i][2]), "r"(a[i][3]),
                          "r"(b[j][0]), "r"(b[j][1]));
                }
        }

        if (it + 1 < nIter) {
            buf ^= 1;
            float* Aw = As + buf * (GBK * 128);
            float* Bw = Bs + buf * (GBK * 128);
#pragma unroll
            for (int jj = 0; jj < 4; jj++) {
                int r = warp * 4 + jj;
                *(float4*)&Aw[r * 128 + ((lane * 4) ^ ((r & 3) << 3))] = aR[jj];
                *(float4*)&Bw[r * 128 + ((lane * 4) ^ ((r & 3) << 3))] = bR[jj];
            }
            __syncthreads();
        }
    }

    // epilogue
#pragma unroll
    for (int i = 0; i < 4; i++) {
        int mr0 = m0 + warp_m + i * 16 + gid;
        int mr1 = mr0 + 8;
#pragma unroll
        for (int j = 0; j < 4; j++) {
            int nc = n0 + warp_n + j * 8 + tig * 2;
            float b0 = bias[nc], b1 = bias[nc + 1];
            if (mr0 < M) {
                C[(size_t)mr0 * GG + nc]     = d[i][j][0] + b0;
                C[(size_t)mr0 * GG + nc + 1] = d[i][j][1] + b1;
            }
            if (mr1 < M) {
                C[(size_t)mr1 * GG + nc]     = d[i][j][2] + b0;
                C[(size_t)mr1 * GG + nc + 1] = d[i][j][3] + b1;
            }
        }
    }
}

// ------------------- TMA / mbarrier helpers -------------------
__device__ __forceinline__ uint32_t smem_u32(const void* p) {
    uint32_t a;
    asm("{ .reg .u64 t; cvta.to.shared.u64 t, %1; cvt.u32.u64 %0, t; }"
        : "=r"(a) : "l"(p));
    return a;
}
__device__ __forceinline__ void mbar_init(uint32_t addr, uint32_t count) {
    asm volatile("mbarrier.init.shared.b64 [%0], %1;" :: "r"(addr), "r"(count) : "memory");
}
__device__ __forceinline__ void mbar_wait(uint32_t addr, uint32_t phase) {
    uint32_t done;
    do {
        asm volatile(
            "{\n\t.reg .pred p;\n\t"
            "mbarrier.try_wait.parity.acquire.cta.shared::cta.b64 p, [%1], %2, 0x989680;\n\t"
            "selp.b32 %0, 1, 0, p;\n\t}"
            : "=r"(done) : "r"(addr), "r"(phase) : "memory");
    } while (!done);
}
__device__ __forceinline__ void mbar_expect(uint32_t mbar, uint32_t bytes) {
    asm volatile("mbarrier.arrive.expect_tx.shared.b64 _, [%0], %1;"
                 :: "r"(mbar), "r"(bytes) : "memory");
}
__device__ __forceinline__ void bulk_cp(uint32_t mbar, uint32_t dst_smem,
                                        const void* src_gmem, uint32_t bytes) {
    asm volatile(
        "cp.async.bulk.shared::cluster.global.mbarrier::complete_tx::bytes "
        "[%0], [%1], %2, [%3];"
        :: "r"(dst_smem), "l"(src_gmem), "r"(bytes), "r"(mbar) : "memory");
}

// ------------------- persistent LSTM layer kernel -------------------
#define NCTA_DIR 64
#define HCHUNK_BYTES (128 * BB * 4)   // 16384 B
#define PRE_SLICE_B (48 * BB * 4)     // 6144 B per step per CTA

__device__ __forceinline__ void dir_barrier(int dir) {
    __threadfence();
    __syncthreads();
    if (threadIdx.x == 0) {
        unsigned my = *(volatile unsigned*)&g_gen[dir];
        unsigned t = atomicAdd(&g_cnt[dir], 1u);
        if (t == NCTA_DIR - 1) {
            g_cnt[dir] = 0;
            __threadfence();
            atomicAdd(&g_gen[dir], 1u);
        } else {
            while (*(volatile unsigned*)&g_gen[dir] == my) { __nanosleep(64); }
            __threadfence();
        }
    }
    __syncthreads();
}

__global__ __launch_bounds__(256) void lstm_persist_kernel(
    const float* __restrict__ preF, const float* __restrict__ preR,
    const float* __restrict__ whhF, const float* __restrict__ whhR,
    float* __restrict__ hout)
{
    extern __shared__ float sm[];
    float* w2_s   = sm;                      // 48*768 interleaved row-pairs
    float* h_s    = w2_s + 48 * DD;          // 3*128*32
    float* gate_s = h_s + 3 * 128 * BB;      // 32*48  [b][r]
    float* c_s    = gate_s + 32 * 48;        // 384
    float* pre_s  = c_s + 384;               // 2*1536 [slot][b*48+r]
    __shared__ __align__(8) unsigned long long mbar_arr[5];

    int tid = threadIdx.x, bid = blockIdx.x;
    int dir = bid >> 6;
    int cta = bid & 63;
    int U0 = cta * 12;
    const float* whh = dir ? whhR : whhF;
    const float* pre = dir ? preR : preF;

    int warp = tid >> 5, lane = tid & 31;
    int r0 = warp * 6;
    int p0 = warp * 3;

    uint32_t mbar0 = smem_u32(&mbar_arr[0]);
    uint32_t hsm0  = smem_u32(h_s);
    uint32_t psm0  = smem_u32(pre_s);

    if (tid == 0) {
        for (int i = 0; i < 5; i++) mbar_init(mbar0 + i * 8, 1);
        int t0 = dir ? (WW - 1) : 0;
        mbar_expect(mbar0 + 3 * 8, PRE_SLICE_B);
        for (int b = 0; b < BB; b++)
            bulk_cp(mbar0 + 3 * 8, psm0 + b * 192,
                    pre + ((size_t)b * WW + t0) * GG + cta * 48, 192);
    }

    for (int idx = tid; idx < 48 * (DD / 4); idx += 256) {
        int r = idx / (DD / 4), k4 = idx % (DD / 4);
        int g = r / 12, u = r % 12;
        float4 v = *(const float4*)(whh + ((size_t)(g * DD + U0 + u)) * DD + k4 * 4);
        float* base = &w2_s[(r >> 1) * (2 * DD) + (k4 * 4) * 2 + (r & 1)];
        base[0] = v.x; base[2] = v.y; base[4] = v.z; base[6] = v.w;
    }
    for (int idx = tid; idx < 12 * BB; idx += 256) c_s[idx] = 0.f;
    __syncthreads();

    uint32_t phbits = 0;
    uint32_t preph = 0;

    for (int s = 0; s < WW; ++s) {
        int t = dir ? (WW - 1 - s) : s;

        if (tid == 0 && s + 1 < WW) {
            int tn = dir ? (WW - 2 - s) : (s + 1);
            int slot = (s + 1) & 1;
            mbar_expect(mbar0 + (3 + slot) * 8, PRE_SLICE_B);
            for (int b = 0; b < BB; b++)
                bulk_cp(mbar0 + (3 + slot) * 8, psm0 + slot * PRE_SLICE_B + b * 192,
                        pre + ((size_t)b * WW + tn) * GG + cta * 48, 192);
        }

        ull acc2[3] = {0ull, 0ull, 0ull};

        if (s > 0) {
            const char* hsrc = (const char*)&g_hT[(s - 1) & 1][dir][0][0];
            if (tid == 0) {
                asm volatile("fence.proxy.async;" ::: "memory");
                mbar_expect(mbar0 + 0, HCHUNK_BYTES);
                bulk_cp(mbar0 + 0, hsm0 + 0 * HCHUNK_BYTES, hsrc + 0 * HCHUNK_BYTES, HCHUNK_BYTES);
                mbar_expect(mbar0 + 8, HCHUNK_BYTES);
                bulk_cp(mbar0 + 8, hsm0 + 1 * HCHUNK_BYTES, hsrc + 1 * HCHUNK_BYTES, HCHUNK_BYTES);
            }
#pragma unroll 1
            for (int c = 0; c < 6; c++) {
                int slot = c % 3;
                mbar_wait(mbar0 + slot * 8, (phbits >> slot) & 1u);
                phbits ^= (1u << slot);
                __syncthreads();
                if (tid == 0 && c < 4) {
                    int s2 = (c + 2) % 3;
                    mbar_expect(mbar0 + s2 * 8, HCHUNK_BYTES);
                    bulk_cp(mbar0 + s2 * 8, hsm0 + s2 * HCHUNK_BYTES,
                            hsrc + (size_t)(c + 2) * HCHUNK_BYTES, HCHUNK_BYTES);
                }
                const float* hb = h_s + slot * (128 * BB);
#pragma unroll 4
                for (int kk = 0; kk < 128; kk += 4) {
                    float h0 = hb[(kk + 0) * BB + lane];
                    float h1 = hb[(kk + 1) * BB + lane];
                    float h2v = hb[(kk + 2) * BB + lane];
                    float h3 = hb[(kk + 3) * BB + lane];
                    ull hp0 = packf2(h0, h0), hp1 = packf2(h1, h1);
                    ull hp2 = packf2(h2v, h2v), hp3 = packf2(h3, h3);
#pragma unroll
                    for (int j2 = 0; j2 < 3; j2++) {
                        const float* wb = &w2_s[(p0 + j2) * (2 * DD) + (c * 128 + kk) * 2];
                        ulonglong2 wv0 = *(const ulonglong2*)(wb);
                        ulonglong2 wv1 = *(const ulonglong2*)(wb + 4);
                        acc2[j2] = fma2(wv0.x, hp0, acc2[j2]);
                        acc2[j2] = fma2(wv0.y, hp1, acc2[j2]);
                        acc2[j2] = fma2(wv1.x, hp2, acc2[j2]);
                        acc2[j2] = fma2(wv1.y, hp3, acc2[j2]);
                    }
                }
            }
        }

#pragma unroll
        for (int j2 = 0; j2 < 3; j2++) {
            float2 v = unpackf2(acc2[j2]);
            gate_s[lane * 48 + r0 + 2 * j2]     = v.x;
            gate_s[lane * 48 + r0 + 2 * j2 + 1] = v.y;
        }
        {
            int slot = s & 1;
            mbar_wait(mbar0 + (3 + slot) * 8, (preph >> slot) & 1u);
            preph ^= (1u << slot);
        }
        __syncthreads();

        const float* ps = pre_s + (s & 1) * (48 * BB);
        for (int item = tid; item < 12 * BB; item += 256) {
            int b = item / 12, u = item % 12;
            float gi = ps[b * 48 + 0 * 12 + u] + gate_s[b * 48 + 0 * 12 + u];
            float gf = ps[b * 48 + 1 * 12 + u] + gate_s[b * 48 + 1 * 12 + u];
            float gg = ps[b * 48 + 2 * 12 + u] + gate_s[b * 48 + 2 * 12 + u];
            float go = ps[b * 48 + 3 * 12 + u] + gate_s[b * 48 + 3 * 12 + u];
            float iv = 1.f / (1.f + expf(-gi));
            float fv = 1.f / (1.f + expf(-gf));
            float gv = tanhf(gg);
            float ov = 1.f / (1.f + expf(-go));
            float cc = fv * c_s[item] + iv * gv;
            c_s[item] = cc;
            float hh = ov * tanhf(cc);
            __stcg(&g_hT[s & 1][dir][U0 + u][b], hh);
            hout[((size_t)(b * WW + t)) * H2 + dir * DD + U0 + u] = hh;
        }

        if (s < WW - 1) dir_barrier(dir);
    }
}

// ------------------- emissions: linear (NT=2) + softmax -------------------
__global__ void emis_kernel(const float* __restrict__ h2,
                            const float* __restrict__ wlin,
                            const float* __restrict__ blin,
                            float* __restrict__ out)
{
    int row = blockIdx.x * 8 + (threadIdx.x >> 5);
    int lane = threadIdx.x & 31;
    if (row >= MROWS) return;
    const float4* hr = (const float4*)(h2 + (size_t)row * H2);
    const float4* w0 = (const float4*)(wlin);
    const float4* w1 = (const float4*)(wlin + H2);
    float a0 = 0.f, a1 = 0.f;
    for (int i = lane; i < H2 / 4; i += 32) {
        float4 hv = hr[i], x0 = w0[i], x1 = w1[i];
        a0 += hv.x * x0.x + hv.y * x0.y + hv.z * x0.z + hv.w * x0.w;
        a1 += hv.x * x1.x + hv.y * x1.y + hv.z * x1.z + hv.w * x1.w;
    }
#pragma unroll
    for (int o = 16; o; o >>= 1) {
        a0 += __shfl_down_sync(0xffffffffu, a0, o);
        a1 += __shfl_down_sync(0xffffffffu, a1, o);
    }
    if (lane == 0) {
        float l0 = a0 + blin[0], l1 = a1 + blin[1];
        float m = fmaxf(l0, l1);
        float e0 = expf(l0 - m), e1 = expf(l1 - m);
        float inv = 1.f / (e0 + e1);
        float p0 = e0 * inv, p1 = e1 * inv;
        g_emis[row * 2] = p0; g_emis[row * 2 + 1] = p1;
        out[MROWS + row * 2] = p0; out[MROWS + row * 2 + 1] = p1;
    }
}

// ------------------- CRF -------------------
__device__ __forceinline__ float lse2(float x, float y) {
    float m = fmaxf(x, y);
    return m + log1pf(expf(fminf(x, y) - m));
}

__global__ void crf_llh_kernel(const int* __restrict__ labels,
                               const float* __restrict__ start,
                               const float* __restrict__ endv,
                               const float* __restrict__ trans,
                               float* __restrict__ out)
{
    int b = threadIdx.x;
    __shared__ float red[BB];
    int mul = g_w64 ? 2 : 1;
    const int* lab = labels + (size_t)b * WW * mul;
    float t00 = trans[0], t01 = trans[1], t10 = trans[2], t11 = trans[3];

    int prev = lab[0];
    float num = start[prev];
    for (int s = 0; s < WW; s++) {
        int tg = lab[s * mul];
        num += g_emis[(b * WW + s) * 2 + tg];
        if (s > 0) num += trans[prev * 2 + tg];
        prev = tg;
    }
    num += endv[prev];

    float a0 = start[0] + g_emis[(b * WW) * 2 + 0];
    float a1 = start[1] + g_emis[(b * WW) * 2 + 1];
    for (int s = 1; s < WW; s++) {
        float e0 = g_emis[(b * WW + s) * 2 + 0];
        float e1 = g_emis[(b * WW + s) * 2 + 1];
        float x0 = lse2(a0 + t00, a1 + t10) + e0;
        float x1 = lse2(a0 + t01, a1 + t11) + e1;
        a0 = x0; a1 = x1;
    }
    float logZ = lse2(a0 + endv[0], a1 + endv[1]);
    red[b] = num - logZ;
    __syncthreads();
    if (b == 0) {
        float sum = 0.f;
        for (int i = 0; i < BB; i++) sum += red[i];
        out[MROWS + MROWS * 2] = -(sum / (float)BB);
    }
}

__global__ void crf_decode_kernel(const float* __restrict__ start,
                                  const float* __restrict__ endv,
                                  const float* __restrict__ trans,
                                  float* __restrict__ out)
{
    int b = threadIdx.x;
    float t00 = trans[0], t01 = trans[1], t10 = trans[2], t11 = trans[3];
    float s0 = start[0] + g_emis[(b * WW) * 2 + 0];
    float s1 = start[1] + g_emis[(b * WW) * 2 + 1];
    for (int s = 1; s < WW; s++) {
        float c00 = s0 + t00, c10 = s1 + t10;
        float c01 = s0 + t01, c11 = s1 + t11;
        unsigned char bp0 = (c10 > c00) ? 1 : 0;
        unsigned char bp1 = (c11 > c01) ? 1 : 0;
        float e0 = g_emis[(b * WW + s) * 2 + 0];
        float e1 = g_emis[(b * WW + s) * 2 + 1];
        float n0 = fmaxf(c00, c10) + e0;
        float n1 = fmaxf(c01, c11) + e1;
        g_bp[b][s][0] = bp0; g_bp[b][s][1] = bp1;
        s0 = n0; s1 = n1;
    }
    int tag = (s1 + endv[1] > s0 + endv[0]) ? 1 : 0;
    out[b * WW + (WW - 1)] = (float)tag;
    for (int s = WW - 1; s >= 1; s--) {
        tag = (int)g_bp[b][s][tag];
        out[b * WW + (s - 1)] = (float)tag;
    }
}

// ------------------- host launcher -------------------
extern "C" void kernel_launch(void* const* d_in, const int* in_sizes, int n_in,
                              void* d_out, int out_size)
{
    const float* bert      = (const float*)d_in[0];
    const int*   words     = (const int*)d_in[1];
    const int*   labels    = (const int*)d_in[2];
    const float* w_ih_l0   = (const float*)d_in[3];
    const float* w_hh_l0   = (const float*)d_in[4];
    const float* b_l0      = (const float*)d_in[5];
    const float* w_ih_l0r  = (const float*)d_in[6];
    const float* w_hh_l0r  = (const float*)d_in[7];
    const float* b_l0r     = (const float*)d_in[8];
    const float* w_ih_l1   = (const float*)d_in[9];
    const float* w_hh_l1   = (const float*)d_in[10];
    const float* b_l1      = (const float*)d_in[11];
    const float* w_ih_l1r  = (const float*)d_in[12];
    const float* w_hh_l1r  = (const float*)d_in[13];
    const float* b_l1r     = (const float*)d_in[14];
    const float* w_lin     = (const float*)d_in[15];
    const float* b_lin     = (const float*)d_in[16];
    const float* crf_start = (const float*)d_in[17];
    const float* crf_end   = (const float*)d_in[18];
    const float* crf_trans = (const float*)d_in[19];
    float* out = (float*)d_out;

    float *pfeat, *ppre0, *ppre1, *ph1, *ph2, *pa3, *pb3f, *pb3r, *pbp0, *pbp1;
    cudaGetSymbolAddress((void**)&pfeat, g_feat);
    cudaGetSymbolAddress((void**)&ppre0, g_pre0);
    cudaGetSymbolAddress((void**)&ppre1, g_pre1);
    cudaGetSymbolAddress((void**)&ph1, g_h1);
    cudaGetSymbolAddress((void**)&ph2, g_h2);
    cudaGetSymbolAddress((void**)&pa3, g_a3);
    cudaGetSymbolAddress((void**)&pb3f, g_b3f);
    cudaGetSymbolAddress((void**)&pb3r, g_b3r);
    cudaGetSymbolAddress((void**)&pbp0, g_bpm0);
    cudaGetSymbolAddress((void**)&pbp1, g_bpm1);

    const int lstm_smem = (48 * DD + 3 * 128 * BB + 32 * 48 + 384 + 2 * 48 * BB) * 4;
    cudaFuncSetAttribute(lstm_persist_kernel,
                         cudaFuncAttributeMaxDynamicSharedMemorySize, lstm_smem);
    const int gemm_smem = 4 * GBK * 128 * 4;   // 65536
    cudaFuncSetAttribute(mma_gemm_kernel,
                         cudaFuncAttributeMaxDynamicSharedMemorySize, gemm_smem);

    detect_kernel<<<1, 256>>>(words);
    firstidx_kernel<<<(MROWS + 255) / 256, 256>>>(words);
    gather_kernel<<<MROWS, 192>>>(bert);

    dim3 tblk(32, 8);
    dim3 ggrid(GG / 128, MP / 128);

    // ---- layer 0 projections (K=768, K3=2304) ----
    splitA_kernel<<<dim3(DD / 32, MROWS / 32), tblk>>>(pfeat, pa3, MROWS, DD);
    splitB_kernel<<<dim3(DD / 32, GG / 32), tblk>>>(w_ih_l0,  b_l0,  pb3f, pbp0, DD);
    splitB_kernel<<<dim3(DD / 32, GG / 32), tblk>>>(w_ih_l0r, b_l0r, pb3r, pbp1, DD);
    mma_gemm_kernel<<<ggrid, 256, gemm_smem>>>(pa3, pb3f, pbp0, ppre0, MROWS, 3 * DD);
    mma_gemm_kernel<<<ggrid, 256, gemm_smem>>>(pa3, pb3r, pbp1, ppre1, MROWS, 3 * DD);

    lstm_persist_kernel<<<128, 256, lstm_smem>>>(ppre0, ppre1, w_hh_l0, w_hh_l0r, ph1);

    // ---- layer 1 projections (K=1536, K3=4608) ----
    splitA_kernel<<<dim3(H2 / 32, MROWS / 32), tblk>>>(ph1, pa3, MROWS, H2);
    splitB_kernel<<<dim3(H2 / 32, GG / 32), tblk>>>(w_ih_l1,  b_l1,  pb3f, pbp0, H2);
    splitB_kernel<<<dim3(H2 / 32, GG / 32), tblk>>>(w_ih_l1r, b_l1r, pb3r, pbp1, H2);
    mma_gemm_kernel<<<ggrid, 256, gemm_smem>>>(pa3, pb3f, pbp0, ppre0, MROWS, 3 * H2);
    mma_gemm_kernel<<<ggrid, 256, gemm_smem>>>(pa3, pb3r, pbp1, ppre1, MROWS, 3 * H2);

    lstm_persist_kernel<<<128, 256, lstm_smem>>>(ppre0, ppre1, w_hh_l1, w_hh_l1r, ph2);

    emis_kernel<<<MROWS / 8, 256>>>(ph2, w_lin, b_lin, out);
    crf_llh_kernel<<<1, BB>>>(labels, crf_start, crf_end, crf_trans, out);
    crf_decode_kernel<<<1, BB>>>(crf_start, crf_end, crf_trans, out);
}